// round 4
// baseline (speedup 1.0000x reference)
#include <cuda_runtime.h>
#include <math.h>

// Shapes (fixed):
//   input        : [4096, 32, 8, 8]  f32
//   edge_sources : [32768]           int32
//   e            : [32768, 32, 8, 8] f32
//   w_node/w_edge: [32, 32, 3, 3]    f32
//   out          : [32768, 32, 8, 8] f32
#define CCH    32
#define TILE   2048          // 32*8*8
#define KW     9216          // 32*32*9
#define NNODES 4096

// Scratch: th = conv3x3(input, w_node). 32 MB, L2-resident during gather.
__device__ float g_th[(size_t)NNODES * TILE];

typedef unsigned long long u64;

__device__ __forceinline__ u64 pack2(float lo, float hi) {
    u64 d; asm("mov.b64 %0, {%1, %2};" : "=l"(d) : "f"(lo), "f"(hi)); return d;
}
__device__ __forceinline__ void unpack2(u64 v, float& lo, float& hi) {
    asm("mov.b64 {%0, %1}, %2;" : "=f"(lo), "=f"(hi) : "l"(v));
}
// Packed dual-fp32 FMA (FFMA2) — ptxas never emits this from C++.
__device__ __forceinline__ void fma2(u64& d, u64 a, u64 b, u64 c) {
    asm("fma.rn.f32x2 %0, %1, %2, %3;" : "=l"(d) : "l"(a), "l"(b), "l"(c));
}

__device__ __forceinline__ float elu1(float v) {
    return v > 0.0f ? v : expm1f(v);
}

// One warp per item; lane = output channel. Each lane computes its full 8x8
// output plane with 32 packed accumulators (f32x2).
// E-row loads are warp-uniform LDG.128 (1 sector/warp). Weight LDS are
// lane-consecutive (conflict-free).
template <bool EDGE>
__global__ __launch_bounds__(256, 2)
void conv_kernel(const float* __restrict__ x,     // [N,32,8,8]
                 const float* __restrict__ w,     // [32,32,3,3]
                 const int*   __restrict__ srcs,  // [E]
                 float*       __restrict__ out)
{
    __shared__ float w_s[KW];   // transposed: w_s[k*32+co]
    const int tid = threadIdx.x;

    for (int i = tid; i < KW; i += 256) {
        int co = i / 288;
        int k  = i - co * 288;
        w_s[k * 32 + co] = w[i];
    }
    __syncthreads();

    const int warp = tid >> 5;
    const int co   = tid & 31;
    const int item = blockIdx.x * 8 + warp;

    const float* xi = x + (size_t)item * TILE;

    // A[y][j]: packed output pair (x=2j, 2j+1) of row y
    u64 A[8][4];
    #pragma unroll
    for (int y = 0; y < 8; y++)
        #pragma unroll
        for (int j = 0; j < 4; j++) A[y][j] = 0ULL;

    #pragma unroll 1
    for (int ci = 0; ci < CCH; ci++) {
        // 9 weights for (co, ci), packed (w,w)
        u64 wp[9];
        #pragma unroll
        for (int t = 0; t < 9; t++) {
            float wv = w_s[(ci * 9 + t) * 32 + co];
            wp[t] = pack2(wv, wv);
        }

        const float4* rowp = (const float4*)(xi + ci * 64);

        #pragma unroll
        for (int yy = 0; yy < 8; yy++) {
            float4 a = __ldg(rowp + yy * 2);
            float4 b = __ldg(rowp + yy * 2 + 1);
            // shifted pair sets for the 3 dx taps:
            //   dx=0 -> E0..E3, dx=1 -> O0..O3, dx=2 -> E1..E4
            u64 O0 = pack2(a.x, a.y), O1 = pack2(a.z, a.w);
            u64 O2 = pack2(b.x, b.y), O3 = pack2(b.z, b.w);
            u64 E0 = pack2(0.f, a.x), E1 = pack2(a.y, a.z);
            u64 E2 = pack2(a.w, b.x), E3 = pack2(b.y, b.z);
            u64 E4 = pack2(b.w, 0.f);

            // input row yy feeds output row y = yy + 1 - dy
            #define ROW3(Ay, base)                                   \
                fma2((Ay)[0], wp[(base)+0], E0, (Ay)[0]);            \
                fma2((Ay)[1], wp[(base)+0], E1, (Ay)[1]);            \
                fma2((Ay)[2], wp[(base)+0], E2, (Ay)[2]);            \
                fma2((Ay)[3], wp[(base)+0], E3, (Ay)[3]);            \
                fma2((Ay)[0], wp[(base)+1], O0, (Ay)[0]);            \
                fma2((Ay)[1], wp[(base)+1], O1, (Ay)[1]);            \
                fma2((Ay)[2], wp[(base)+1], O2, (Ay)[2]);            \
                fma2((Ay)[3], wp[(base)+1], O3, (Ay)[3]);            \
                fma2((Ay)[0], wp[(base)+2], E1, (Ay)[0]);            \
                fma2((Ay)[1], wp[(base)+2], E2, (Ay)[1]);            \
                fma2((Ay)[2], wp[(base)+2], E3, (Ay)[2]);            \
                fma2((Ay)[3], wp[(base)+2], E4, (Ay)[3]);

            ROW3(A[yy], 3)                      // dy=1 (y = yy)
            if (yy < 7) { ROW3(A[yy + 1], 0) }  // dy=0 (y = yy+1)
            if (yy > 0) { ROW3(A[yy - 1], 6) }  // dy=2 (y = yy-1)
            #undef ROW3
        }
    }

    if (EDGE) {
        const int src = srcs[item];
        const float4* th4 = (const float4*)(g_th + (size_t)src * TILE + co * 64);
        float4*       op4 = (float4*)(out + (size_t)item * TILE + co * 64);
        #pragma unroll
        for (int y = 0; y < 8; y++) {
            float4 t0 = __ldg(th4 + y * 2);
            float4 t1 = __ldg(th4 + y * 2 + 1);
            float a0,a1,a2,a3,a4,a5,a6,a7;
            unpack2(A[y][0], a0, a1); unpack2(A[y][1], a2, a3);
            unpack2(A[y][2], a4, a5); unpack2(A[y][3], a6, a7);
            op4[y * 2]     = make_float4(elu1(t0.x*a0), elu1(t0.y*a1),
                                         elu1(t0.z*a2), elu1(t0.w*a3));
            op4[y * 2 + 1] = make_float4(elu1(t1.x*a4), elu1(t1.y*a5),
                                         elu1(t1.z*a6), elu1(t1.w*a7));
        }
    } else {
        float4* op4 = (float4*)(g_th + (size_t)item * TILE + co * 64);
        #pragma unroll
        for (int y = 0; y < 8; y++) {
            float a0,a1,a2,a3,a4,a5,a6,a7;
            unpack2(A[y][0], a0, a1); unpack2(A[y][1], a2, a3);
            unpack2(A[y][2], a4, a5); unpack2(A[y][3], a6, a7);
            op4[y * 2]     = make_float4(a0, a1, a2, a3);
            op4[y * 2 + 1] = make_float4(a4, a5, a6, a7);
        }
    }
}

extern "C" void kernel_launch(void* const* d_in, const int* in_sizes, int n_in,
                              void* d_out, int out_size)
{
    const float* input  = (const float*)d_in[0];
    const int*   srcs   = (const int*)  d_in[1];
    const float* e      = (const float*)d_in[2];
    const float* w_node = (const float*)d_in[3];
    const float* w_edge = (const float*)d_in[4];
    float*       out    = (float*)d_out;

    const int n_nodes = in_sizes[0] / TILE;   // 4096
    const int n_edges = in_sizes[2] / TILE;   // 32768

    // 1) node conv -> g_th
    conv_kernel<false><<<n_nodes / 8, 256>>>(input, w_node, nullptr, nullptr);
    // 2) edge conv + gather(th) + elu -> out
    conv_kernel<true><<<n_edges / 8, 256>>>(e, w_edge, srcs, out);
}

// round 8
// speedup vs baseline: 2.0660x; 2.0660x over previous
#include <cuda_runtime.h>
#include <cuda_bf16.h>
#include <cstdint>
#include <math.h>

// Shapes: input [4096,32,8,8] f32 | edge_sources [32768] i32 | e [32768,32,8,8] f32
//         w_* [32,32,3,3] f32 | out [32768,32,8,8] f32
#define TILE   2048
#define NNODES 4096
__device__ float g_th[(size_t)NNODES * TILE];

typedef uint32_t u32;

// ---- smem layout (bytes) ----
// A (weights, bf16 pairs): [tap9][co32 (stride 20 u32)][ciPair16] -> 5760 u32
#define AH_OFF 0u
#define AL_OFF 23040u
// B (per warp): [ciPair16 (stride 104 u32)][pix 10x10 padded] -> 1664 u32; hi+lo
#define B_OFF  46080u
#define B_WARP 3328u            // u32 per warp (hi 1664 + lo 1664)
#define SMEM_BYTES (46080u + 8u * B_WARP * 4u)   // 152576

#define MMA(dd, A0, A1, A2, A3, B0, B1)                                          \
    asm volatile("mma.sync.aligned.m16n8k16.row.col.f32.bf16.bf16.f32 "          \
                 "{%0,%1,%2,%3}, {%4,%5,%6,%7}, {%8,%9}, {%0,%1,%2,%3};"         \
                 : "+f"((dd)[0]), "+f"((dd)[1]), "+f"((dd)[2]), "+f"((dd)[3])    \
                 : "r"(A0), "r"(A1), "r"(A2), "r"(A3), "r"(B0), "r"(B1))

__device__ __forceinline__ float elu1(float v) { return v > 0.0f ? v : expm1f(v); }

__device__ __forceinline__ void split_bf16(float v, unsigned short& h, unsigned short& l) {
    __nv_bfloat16 hb = __float2bfloat16(v);
    __nv_bfloat16 lb = __float2bfloat16(v - __bfloat162float(hb));
    h = __bfloat16_as_ushort(hb);
    l = __bfloat16_as_ushort(lb);
}

// One warp per item. D[32co, 64px] via m16n8k16 bf16 mma, 3-pass hi/lo split.
template <bool EDGE>
__global__ __launch_bounds__(256, 1)
void mma_conv(const float* __restrict__ x,     // [N,32,8,8]
              const float* __restrict__ w,     // [32,32,3,3]
              const int*   __restrict__ srcs,  // [E] (EDGE only)
              float*       __restrict__ out,   // EDGE only
              int nitems)
{
    extern __shared__ char smem[];
    const int tid  = threadIdx.x;
    const int wid  = tid >> 5;
    const int lane = tid & 31;
    const int row  = lane >> 2;   // fragment group id (A/D row, B col)
    const int quad = lane & 3;    // fragment thread-in-group

    // ---- one-time: weights -> A_hi / A_lo, [tap][co*20 + ciPair] bf16 pairs ----
    for (int i = tid; i < 9216; i += 256) {
        int co = i / 288, r = i - co * 288;
        int ci = r / 9,   tap = r - ci * 9;
        unsigned short h, l;
        split_bf16(w[i], h, l);
        u32 boff = ((u32)(tap * 32 + co) * 20 + (ci >> 1)) * 4 + (ci & 1) * 2;
        *(unsigned short*)(smem + AH_OFF + boff) = h;
        *(unsigned short*)(smem + AL_OFF + boff) = l;
    }
    // ---- one-time: zero all B tiles (borders stay zero forever) ----
    for (u32 i = tid; i < 8 * B_WARP; i += 256)
        ((u32*)(smem + B_OFF))[i] = 0;
    __syncthreads();

    const u32* AH = (const u32*)(smem + AH_OFF);
    const u32* AL = (const u32*)(smem + AL_OFF);
    u32* BH = (u32*)(smem + B_OFF) + wid * B_WARP;
    u32* BL = BH + 1664;

    for (int item = blockIdx.x * 8 + wid; item < nitems; item += gridDim.x * 8) {
        // ---- B fill: padded 10x10 pixel field, ci pairs packed in u32 ----
        const float* ei = x + (size_t)item * TILE;
        #pragma unroll
        for (int t = 0; t < 32; t++) {
            int i  = t * 32 + lane;
            int cp = i >> 6, px = i & 63;
            float v0 = __ldg(ei + cp * 128 + px);        // ci = 2cp
            float v1 = __ldg(ei + cp * 128 + 64 + px);   // ci = 2cp+1
            unsigned short h0, l0, h1, l1;
            split_bf16(v0, h0, l0);
            split_bf16(v1, h1, l1);
            int py = px >> 3, pxx = px & 7;
            int pidx = cp * 104 + (py + 1) * 10 + pxx + 1;
            BH[pidx] = ((u32)h1 << 16) | h0;
            BL[pidx] = ((u32)l1 << 16) | l0;
        }
        __syncwarp();

        // ---- accumulators ----
        float d[2][8][4];
        #pragma unroll
        for (int m = 0; m < 2; m++)
            #pragma unroll
            for (int n = 0; n < 8; n++)
                #pragma unroll
                for (int j = 0; j < 4; j++) d[m][n][j] = 0.0f;

        // ---- 3 passes x 9 taps x 2 ksteps x (2 M x 8 N) mmas ----
        #pragma unroll 1
        for (int pass = 0; pass < 3; pass++) {
            const u32* Ap = (pass == 2) ? AL : AH;
            const u32* Bp = (pass == 1) ? BL : BH;
            #pragma unroll 1
            for (int tap = 0; tap < 9; tap++) {
                const int dy = tap / 3, dx = tap - dy * 3;
                const int pix_off = dy * 10 + dx + row;   // B col = row group
                #pragma unroll
                for (int ks = 0; ks < 2; ks++) {
                    const u32* ab = Ap + (u32)(tap * 32) * 20 + ks * 8 + quad;
                    u32 a0 = ab[row * 20],        a1 = ab[(row + 8) * 20];
                    u32 a2 = ab[row * 20 + 4],    a3 = ab[(row + 8) * 20 + 4];
                    u32 a4 = ab[(row + 16) * 20], a5 = ab[(row + 24) * 20];
                    u32 a6 = ab[(row + 16) * 20 + 4], a7 = ab[(row + 24) * 20 + 4];
                    const u32* bb = Bp + (u32)(ks * 8 + quad) * 104 + pix_off;
                    #pragma unroll
                    for (int n = 0; n < 8; n++) {
                        u32 b0 = bb[n * 10];
                        u32 b1 = bb[n * 10 + 416];   // ciPair + 4
                        MMA(d[0][n], a0, a1, a2, a3, b0, b1);
                        MMA(d[1][n], a4, a5, a6, a7, b0, b1);
                    }
                }
            }
        }

        // ---- epilogue ----
        // thread owns co in {m*16+row, m*16+row+8}, y = n, x in {2q, 2q+1}
        if (EDGE) {
            const int src = __ldg(srcs + item);
            const float* thp = g_th + (size_t)src * TILE;
            float* op = out + (size_t)item * TILE;
            #pragma unroll
            for (int m = 0; m < 2; m++) {
                const int co0 = m * 16 + row, co1 = co0 + 8;
                #pragma unroll
                for (int n = 0; n < 8; n++) {
                    const int pb = n * 8 + 2 * quad;
                    float2 t0 = *(const float2*)(thp + co0 * 64 + pb);
                    float2 t1 = *(const float2*)(thp + co1 * 64 + pb);
                    float2 o0, o1;
                    o0.x = elu1(t0.x * d[m][n][0]);
                    o0.y = elu1(t0.y * d[m][n][1]);
                    o1.x = elu1(t1.x * d[m][n][2]);
                    o1.y = elu1(t1.y * d[m][n][3]);
                    *(float2*)(op + co0 * 64 + pb) = o0;
                    *(float2*)(op + co1 * 64 + pb) = o1;
                }
            }
        } else {
            float* op = g_th + (size_t)item * TILE;
            #pragma unroll
            for (int m = 0; m < 2; m++) {
                const int co0 = m * 16 + row, co1 = co0 + 8;
                #pragma unroll
                for (int n = 0; n < 8; n++) {
                    const int pb = n * 8 + 2 * quad;
                    *(float2*)(op + co0 * 64 + pb) = make_float2(d[m][n][0], d[m][n][1]);
                    *(float2*)(op + co1 * 64 + pb) = make_float2(d[m][n][2], d[m][n][3]);
                }
            }
        }
        __syncwarp();
    }
}

extern "C" void kernel_launch(void* const* d_in, const int* in_sizes, int n_in,
                              void* d_out, int out_size)
{
    const float* input  = (const float*)d_in[0];
    const int*   srcs   = (const int*)  d_in[1];
    const float* e      = (const float*)d_in[2];
    const float* w_node = (const float*)d_in[3];
    const float* w_edge = (const float*)d_in[4];
    float*       outp   = (float*)d_out;

    const int n_nodes = in_sizes[0] / TILE;   // 4096
    const int n_edges = in_sizes[2] / TILE;   // 32768

    cudaFuncSetAttribute(mma_conv<false>, cudaFuncAttributeMaxDynamicSharedMemorySize, SMEM_BYTES);
    cudaFuncSetAttribute(mma_conv<true>,  cudaFuncAttributeMaxDynamicSharedMemorySize, SMEM_BYTES);

    mma_conv<false><<<148, 256, SMEM_BYTES>>>(input, w_node, nullptr, nullptr, n_nodes);
    mma_conv<true><<<148, 256, SMEM_BYTES>>>(e, w_edge, srcs, outp, n_edges);
}

// round 10
// speedup vs baseline: 2.1740x; 1.0523x over previous
#include <cuda_runtime.h>
#include <cuda_bf16.h>
#include <cstdint>
#include <math.h>

// Shapes: input [4096,32,8,8] f32 | edge_sources [32768] i32 | e [32768,32,8,8] f32
//         w_* [32,32,3,3] f32 | out [32768,32,8,8] f32
#define TILE   2048
#define NNODES 4096
__device__ float g_th[(size_t)NNODES * TILE];

typedef uint32_t u32;
typedef unsigned short u16;

// ---- smem u32-offsets ----
// A: [tap9][co32][24 slots] u32; slot = ks*8 + quad*2 + hh holds ciPair (ks*8+quad+4*hh)
#define AH_U   0u
#define AL_U   6912u          // 9*32*24
// B per item: hi [100 pix][24 slots] + lo: 4800 u32
#define B_U    13824u
#define B_ITEM 4800u
#define SMEM_BYTES ((13824u + 8u * 4800u) * 4u)   // 208896 B

#define MMA(dd, A0, A1, A2, A3, B0, B1)                                          \
    asm volatile("mma.sync.aligned.m16n8k16.row.col.f32.bf16.bf16.f32 "          \
                 "{%0,%1,%2,%3}, {%4,%5,%6,%7}, {%8,%9}, {%0,%1,%2,%3};"         \
                 : "+f"((dd)[0]), "+f"((dd)[1]), "+f"((dd)[2]), "+f"((dd)[3])    \
                 : "r"(A0), "r"(A1), "r"(A2), "r"(A3), "r"(B0), "r"(B1))

__device__ __forceinline__ float elu1(float v) { return v > 0.0f ? v : expm1f(v); }

__device__ __forceinline__ void split_bf16(float v, u16& h, u16& l) {
    __nv_bfloat16 hb = __float2bfloat16(v);
    __nv_bfloat16 lb = __float2bfloat16(v - __bfloat162float(hb));
    h = __bfloat16_as_ushort(hb);
    l = __bfloat16_as_ushort(lb);
}

// Warp-pair per item: warp computes all 32 co x 32 pixels (its y-half).
// 3-pass bf16 hi/lo split (drop lo*lo). LDS.64 fragment loads, stride-24 layout.
template <bool EDGE>
__global__ __launch_bounds__(512, 1)
void mma_conv(const float* __restrict__ x,     // [N,32,8,8]
              const float* __restrict__ w,     // [32,32,3,3]
              const int*   __restrict__ srcs,  // [E] (EDGE only)
              float*       __restrict__ out,
              int nitems)
{
    extern __shared__ __align__(16) u32 S[];
    const int tid  = threadIdx.x;
    const int wid  = tid >> 5;
    const int lane = tid & 31;
    const int row  = lane >> 2;
    const int quad = lane & 3;
    const int pr   = wid >> 1;     // pair id 0..7
    const int nh   = wid & 1;      // y-half

    // ---- one-time: weights -> A hi/lo (paired-slot layout) ----
    for (int i = tid; i < 9216; i += 512) {
        int co = i / 288, r = i - co * 288;
        int ci = r / 9,   tap = r - ci * 9;
        u16 h, l;
        split_bf16(w[i], h, l);
        int j = ci >> 1, odd = ci & 1;
        int ks = j >> 3, jq = j & 7, q = jq & 3, hh = jq >> 2;
        u32 idx = (u32)(tap * 32 + co) * 24 + ks * 8 + q * 2 + hh;
        *(u16*)((char*)S + (size_t)(AH_U + idx) * 4 + odd * 2) = h;
        *(u16*)((char*)S + (size_t)(AL_U + idx) * 4 + odd * 2) = l;
    }
    // ---- one-time: zero B region (borders stay zero) ----
    for (u32 i = tid; i < 8 * B_ITEM; i += 512) S[B_U + i] = 0;
    __syncthreads();

    u32* Bh = S + B_U + (u32)pr * B_ITEM;
    u32* Bl = Bh + 2400;
    const int t2  = tid & 63;                                   // pixel within item
    const int p24 = (((t2 >> 3) + 1) * 10 + (t2 & 7) + 1) * 24; // interior pix * 24

    for (int item = blockIdx.x * 8 + pr; item < nitems; item += gridDim.x * 8) {
        // ---- B fill: this thread's pixel, 16 ciPairs hi+lo ----
        const float* ei = x + (size_t)item * TILE;
        #pragma unroll
        for (int j = 0; j < 16; j++) {
            float v0 = __ldg(ei + (2 * j) * 64 + t2);
            float v1 = __ldg(ei + (2 * j + 1) * 64 + t2);
            u16 h0, l0, h1, l1;
            split_bf16(v0, h0, l0);
            split_bf16(v1, h1, l1);
            int ks = j >> 3, jq = j & 7, q = jq & 3, hh = jq >> 2;
            int slot = ks * 8 + q * 2 + hh;
            Bh[p24 + slot] = ((u32)h1 << 16) | h0;
            Bl[p24 + slot] = ((u32)l1 << 16) | l0;
        }
        asm volatile("bar.sync %0, 64;" :: "r"(pr + 1) : "memory");

        float d[2][4][4];
        #pragma unroll
        for (int m = 0; m < 2; m++)
            #pragma unroll
            for (int n = 0; n < 4; n++)
                #pragma unroll
                for (int k = 0; k < 4; k++) d[m][n][k] = 0.0f;

        #pragma unroll 1
        for (int tap = 0; tap < 9; tap++) {
            const int dy = tap / 3, dx = tap - dy * 3;
            const u32 pixb = (u32)(dy * 10 + dx + row + nh * 40) * 24;
            #pragma unroll
            for (int ks = 0; ks < 2; ks++) {
                const u32* ap = S + AH_U + (u32)tap * 768 + (u32)row * 24 + ks * 8 + quad * 2;
                uint2 h01 = *(const uint2*)(ap);
                uint2 h23 = *(const uint2*)(ap + 192);
                uint2 h45 = *(const uint2*)(ap + 384);
                uint2 h67 = *(const uint2*)(ap + 576);
                const u32* alp = ap + AL_U;
                uint2 l01 = *(const uint2*)(alp);
                uint2 l23 = *(const uint2*)(alp + 192);
                uint2 l45 = *(const uint2*)(alp + 384);
                uint2 l67 = *(const uint2*)(alp + 576);
                const u32* bp = Bh + pixb + ks * 8 + quad * 2;
                #pragma unroll
                for (int n = 0; n < 4; n++) {
                    uint2 bh = *(const uint2*)(bp + n * 240);
                    uint2 bl = *(const uint2*)(bp + n * 240 + 2400);
                    MMA(d[0][n], h01.x, h23.x, h01.y, h23.y, bh.x, bh.y); // wh*eh
                    MMA(d[1][n], h45.x, h67.x, h45.y, h67.y, bh.x, bh.y);
                    MMA(d[0][n], h01.x, h23.x, h01.y, h23.y, bl.x, bl.y); // wh*el
                    MMA(d[1][n], h45.x, h67.x, h45.y, h67.y, bl.x, bl.y);
                    MMA(d[0][n], l01.x, l23.x, l01.y, l23.y, bh.x, bh.y); // wl*eh
                    MMA(d[1][n], l45.x, l67.x, l45.y, l67.y, bh.x, bh.y);
                }
            }
        }

        // ---- epilogue: co = m*16+row (+8), y = nh*4+n, x = 2quad..+1 ----
        if (EDGE) {
            const int src = __ldg(srcs + item);
            const float* thp = g_th + (size_t)src * TILE;
            float* op = out + (size_t)item * TILE;
            #pragma unroll
            for (int m = 0; m < 2; m++) {
                const int co0 = m * 16 + row, co1 = co0 + 8;
                #pragma unroll
                for (int n = 0; n < 4; n++) {
                    const int pb = (nh * 4 + n) * 8 + 2 * quad;
                    float2 t0 = *(const float2*)(thp + co0 * 64 + pb);
                    float2 t1 = *(const float2*)(thp + co1 * 64 + pb);
                    *(float2*)(op + co0 * 64 + pb) =
                        make_float2(elu1(t0.x * d[m][n][0]), elu1(t0.y * d[m][n][1]));
                    *(float2*)(op + co1 * 64 + pb) =
                        make_float2(elu1(t1.x * d[m][n][2]), elu1(t1.y * d[m][n][3]));
                }
            }
        } else {
            float* op = g_th + (size_t)item * TILE;
            #pragma unroll
            for (int m = 0; m < 2; m++) {
                const int co0 = m * 16 + row, co1 = co0 + 8;
                #pragma unroll
                for (int n = 0; n < 4; n++) {
                    const int pb = (nh * 4 + n) * 8 + 2 * quad;
                    *(float2*)(op + co0 * 64 + pb) = make_float2(d[m][n][0], d[m][n][1]);
                    *(float2*)(op + co1 * 64 + pb) = make_float2(d[m][n][2], d[m][n][3]);
                }
            }
        }
        asm volatile("bar.sync %0, 64;" :: "r"(pr + 1) : "memory");
    }
}

extern "C" void kernel_launch(void* const* d_in, const int* in_sizes, int n_in,
                              void* d_out, int out_size)
{
    const float* input  = (const float*)d_in[0];
    const int*   srcs   = (const int*)  d_in[1];
    const float* e      = (const float*)d_in[2];
    const float* w_node = (const float*)d_in[3];
    const float* w_edge = (const float*)d_in[4];
    float*       outp   = (float*)d_out;

    const int n_nodes = in_sizes[0] / TILE;   // 4096
    const int n_edges = in_sizes[2] / TILE;   // 32768

    cudaFuncSetAttribute(mma_conv<false>, cudaFuncAttributeMaxDynamicSharedMemorySize, SMEM_BYTES);
    cudaFuncSetAttribute(mma_conv<true>,  cudaFuncAttributeMaxDynamicSharedMemorySize, SMEM_BYTES);

    mma_conv<false><<<148, 512, SMEM_BYTES>>>(input, w_node, nullptr, nullptr, n_nodes);
    mma_conv<true><<<148, 512, SMEM_BYTES>>>(e, w_edge, srcs, outp, n_edges);
}